// round 1
// baseline (speedup 1.0000x reference)
#include <cuda_runtime.h>
#include <math.h>

#define TT   4096      // tokens
#define DN   1024      // model dim
#define HN   2048      // hidden dim
#define NE   8         // experts
#define EPSV 1e-5f

#define TM   64        // rows per tile
#define BK   32        // k-chunk
#define TN   128       // cols per chunk
#define NTH  256

// ---------------- scratch (device globals; no allocation allowed) ----------
__device__ int   g_cnt[NE];
__device__ int   g_list[NE * TT];            // assignment ids grouped by expert
__device__ float g_wk[TT * 2];               // combine weight per assignment
__device__ unsigned char g_eid[TT * 2];      // expert id per assignment
__device__ float g_sums[TT * 2 * 2];         // per-assignment sum, sumsq over H
__device__ float g_h[(size_t)TT * 2 * HN];   // 64 MB: h (pre-LN -> post-gelu)
__device__ float g_y[(size_t)TT * 2 * DN];   // 32 MB: expert outputs

// ---------------- 0: zero counters/stats -----------------------------------
__global__ void zero_kernel() {
    int tid = blockIdx.x * blockDim.x + threadIdx.x;
    if (tid < NE) g_cnt[tid] = 0;
    for (int i = tid; i < TT * 2 * 2; i += gridDim.x * blockDim.x) g_sums[i] = 0.f;
}

// ---------------- 1: gating (one warp per token) ----------------------------
__global__ __launch_bounds__(256) void gate_kernel(const float* __restrict__ x,
                                                   const float* __restrict__ gw) {
    int t = blockIdx.x * 8 + (threadIdx.x >> 5);
    if (t >= TT) return;
    int lane = threadIdx.x & 31;
    float acc[NE];
#pragma unroll
    for (int e = 0; e < NE; e++) acc[e] = 0.f;
    const float* xr = x + (size_t)t * DN;
    for (int i = lane; i < DN; i += 32) {
        float xv = xr[i];
        const float4 ga = *(const float4*)(gw + (size_t)i * NE);
        const float4 gb = *(const float4*)(gw + (size_t)i * NE + 4);
        acc[0] = fmaf(xv, ga.x, acc[0]); acc[1] = fmaf(xv, ga.y, acc[1]);
        acc[2] = fmaf(xv, ga.z, acc[2]); acc[3] = fmaf(xv, ga.w, acc[3]);
        acc[4] = fmaf(xv, gb.x, acc[4]); acc[5] = fmaf(xv, gb.y, acc[5]);
        acc[6] = fmaf(xv, gb.z, acc[6]); acc[7] = fmaf(xv, gb.w, acc[7]);
    }
#pragma unroll
    for (int e = 0; e < NE; e++)
        for (int off = 16; off; off >>= 1)
            acc[e] += __shfl_xor_sync(0xffffffffu, acc[e], off);
    if (lane == 0) {
        int i0 = 0; float v0 = acc[0];
#pragma unroll
        for (int e = 1; e < NE; e++) if (acc[e] > v0) { v0 = acc[e]; i0 = e; }
        int i1 = -1; float v1 = -1e30f;
#pragma unroll
        for (int e = 0; e < NE; e++) if (e != i0 && acc[e] > v1) { v1 = acc[e]; i1 = e; }
        // renormalized top-2 softmax weights == softmax over the two logits
        float ee = __expf(v1 - v0);
        float w0 = 1.f / (1.f + ee);
        float w1 = ee / (1.f + ee);
        int id0 = t * 2, id1 = t * 2 + 1;
        g_wk[id0] = w0; g_wk[id1] = w1;
        g_eid[id0] = (unsigned char)i0; g_eid[id1] = (unsigned char)i1;
        int s0 = atomicAdd(&g_cnt[i0], 1); g_list[i0 * TT + s0] = id0;
        int s1 = atomicAdd(&g_cnt[i1], 1); g_list[i1 * TT + s1] = id1;
    }
}

// ---------------- 2: ffn1  h = x @ w1[e] + b1  (+ row stats) ----------------
__global__ __launch_bounds__(NTH) void ffn1_kernel(const float* __restrict__ x,
                                                   const float* __restrict__ w1,
                                                   const float* __restrict__ b1) {
    const int e = blockIdx.y;
    const int cnt = g_cnt[e];
    const int rowbase = blockIdx.x * TM;
    if (rowbase >= cnt) return;
    const int hbase = blockIdx.z * (HN / 2);

    __shared__ __align__(16) float xs[BK][TM + 4];
    __shared__ __align__(16) float ws[BK][TN];
    __shared__ int rows[TM];

    const int tid = threadIdx.x;
    if (tid < TM) {
        int r = rowbase + tid;
        rows[tid] = (r < cnt) ? g_list[e * TT + r] : -1;
    }
    __syncthreads();

    const int tx = tid & 15, ty = tid >> 4;
    const int lrow = tid >> 2;            // x-load: row 0..63
    const int lkq  = (tid & 3) * 8;       // x-load: 8 consecutive k
    const int lkk  = tid >> 3;            // w-load: k row 0..31
    const int lcq  = (tid & 7) * 16;      // w-load: 16 consecutive cols
    const int lid  = rows[lrow];
    const float* xrow = x + (size_t)((lid < 0) ? 0 : (lid >> 1)) * DN + lkq;
    const float* w1e  = w1 + (size_t)e * DN * HN;

    float rsum[4] = {0, 0, 0, 0}, rsq[4] = {0, 0, 0, 0};

    for (int nc = 0; nc < (HN / 2) / TN; ++nc) {
        const int n0 = hbase + nc * TN;
        float c[4][8];
#pragma unroll
        for (int i = 0; i < 4; i++)
#pragma unroll
            for (int j = 0; j < 8; j++) c[i][j] = 0.f;

        for (int k0 = 0; k0 < DN; k0 += BK) {
            __syncthreads();
            float4 a0 = *(const float4*)(xrow + k0);
            float4 a1 = *(const float4*)(xrow + k0 + 4);
            xs[lkq + 0][lrow] = a0.x; xs[lkq + 1][lrow] = a0.y;
            xs[lkq + 2][lrow] = a0.z; xs[lkq + 3][lrow] = a0.w;
            xs[lkq + 4][lrow] = a1.x; xs[lkq + 5][lrow] = a1.y;
            xs[lkq + 6][lrow] = a1.z; xs[lkq + 7][lrow] = a1.w;
            const float* wp = w1e + (size_t)(k0 + lkk) * HN + n0 + lcq;
            *(float4*)&ws[lkk][lcq + 0]  = *(const float4*)(wp + 0);
            *(float4*)&ws[lkk][lcq + 4]  = *(const float4*)(wp + 4);
            *(float4*)&ws[lkk][lcq + 8]  = *(const float4*)(wp + 8);
            *(float4*)&ws[lkk][lcq + 12] = *(const float4*)(wp + 12);
            __syncthreads();
#pragma unroll
            for (int kk = 0; kk < BK; ++kk) {
                float4 av  = *(const float4*)&xs[kk][ty * 4];
                float4 bv0 = *(const float4*)&ws[kk][tx * 8];
                float4 bv1 = *(const float4*)&ws[kk][tx * 8 + 4];
                float ar[4] = {av.x, av.y, av.z, av.w};
                float br[8] = {bv0.x, bv0.y, bv0.z, bv0.w, bv1.x, bv1.y, bv1.z, bv1.w};
#pragma unroll
                for (int i = 0; i < 4; i++)
#pragma unroll
                    for (int j = 0; j < 8; j++) c[i][j] = fmaf(ar[i], br[j], c[i][j]);
            }
        }
        // bias + store + stats
        const int gcol = n0 + tx * 8;
        float4 bb0 = *(const float4*)(b1 + (size_t)e * HN + gcol);
        float4 bb1 = *(const float4*)(b1 + (size_t)e * HN + gcol + 4);
        const float brr[8] = {bb0.x, bb0.y, bb0.z, bb0.w, bb1.x, bb1.y, bb1.z, bb1.w};
#pragma unroll
        for (int rr = 0; rr < 4; ++rr) {
            int id = rows[ty * 4 + rr];
            float v[8]; float ls = 0.f, lq = 0.f;
#pragma unroll
            for (int j = 0; j < 8; j++) {
                v[j] = c[rr][j] + brr[j];
                ls += v[j]; lq += v[j] * v[j];
            }
            rsum[rr] += ls; rsq[rr] += lq;
            if (id >= 0) {
                float4* dst = (float4*)(g_h + (size_t)id * HN + gcol);
                dst[0] = make_float4(v[0], v[1], v[2], v[3]);
                dst[1] = make_float4(v[4], v[5], v[6], v[7]);
            }
        }
    }
    // reduce partial stats across the 16 tx threads (same ty)
#pragma unroll
    for (int rr = 0; rr < 4; ++rr) {
        float s = rsum[rr], q = rsq[rr];
        for (int off = 8; off; off >>= 1) {
            s += __shfl_down_sync(0xffffffffu, s, off, 16);
            q += __shfl_down_sync(0xffffffffu, q, off, 16);
        }
        if (tx == 0) {
            int id = rows[ty * 4 + rr];
            if (id >= 0) {
                atomicAdd(&g_sums[2 * id + 0], s);
                atomicAdd(&g_sums[2 * id + 1], q);
            }
        }
    }
}

// ---------------- 3: LN1 + exact GeLU in place ------------------------------
__global__ __launch_bounds__(256) void act_kernel(const float* __restrict__ ln1_g,
                                                  const float* __restrict__ ln1_b) {
    const int id = blockIdx.x;
    const int e  = g_eid[id];
    float sum  = g_sums[2 * id], sq = g_sums[2 * id + 1];
    float mean = sum * (1.f / HN);
    float var  = sq * (1.f / HN) - mean * mean;
    float rstd = rsqrtf(var + EPSV);
    float* hr = g_h + (size_t)id * HN;
    const float* gg = ln1_g + (size_t)e * HN;
    const float* bb = ln1_b + (size_t)e * HN;
    for (int i = threadIdx.x; i < HN; i += blockDim.x) {
        float v = (hr[i] - mean) * rstd * gg[i] + bb[i];
        hr[i] = v * normcdff(v);     // exact gelu
    }
}

// ---------------- 4: ffn2  y = h @ w2[e] + b2 -------------------------------
__global__ __launch_bounds__(NTH) void ffn2_kernel(const float* __restrict__ w2,
                                                   const float* __restrict__ b2) {
    const int e = blockIdx.y;
    const int cnt = g_cnt[e];
    const int rowbase = blockIdx.x * TM;
    if (rowbase >= cnt) return;
    const int nbase = blockIdx.z * (DN / 2);

    __shared__ __align__(16) float xs[BK][TM + 4];
    __shared__ __align__(16) float ws[BK][TN];
    __shared__ int rows[TM];

    const int tid = threadIdx.x;
    if (tid < TM) {
        int r = rowbase + tid;
        rows[tid] = (r < cnt) ? g_list[e * TT + r] : -1;
    }
    __syncthreads();

    const int tx = tid & 15, ty = tid >> 4;
    const int lrow = tid >> 2;
    const int lkq  = (tid & 3) * 8;
    const int lkk  = tid >> 3;
    const int lcq  = (tid & 7) * 16;
    const int lid  = rows[lrow];
    const float* arow = g_h + (size_t)((lid < 0) ? 0 : lid) * HN + lkq;
    const float* w2e  = w2 + (size_t)e * HN * DN;

    for (int nc = 0; nc < (DN / 2) / TN; ++nc) {
        const int n0 = nbase + nc * TN;
        float c[4][8];
#pragma unroll
        for (int i = 0; i < 4; i++)
#pragma unroll
            for (int j = 0; j < 8; j++) c[i][j] = 0.f;

        for (int k0 = 0; k0 < HN; k0 += BK) {
            __syncthreads();
            float4 a0 = *(const float4*)(arow + k0);
            float4 a1 = *(const float4*)(arow + k0 + 4);
            xs[lkq + 0][lrow] = a0.x; xs[lkq + 1][lrow] = a0.y;
            xs[lkq + 2][lrow] = a0.z; xs[lkq + 3][lrow] = a0.w;
            xs[lkq + 4][lrow] = a1.x; xs[lkq + 5][lrow] = a1.y;
            xs[lkq + 6][lrow] = a1.z; xs[lkq + 7][lrow] = a1.w;
            const float* wp = w2e + (size_t)(k0 + lkk) * DN + n0 + lcq;
            *(float4*)&ws[lkk][lcq + 0]  = *(const float4*)(wp + 0);
            *(float4*)&ws[lkk][lcq + 4]  = *(const float4*)(wp + 4);
            *(float4*)&ws[lkk][lcq + 8]  = *(const float4*)(wp + 8);
            *(float4*)&ws[lkk][lcq + 12] = *(const float4*)(wp + 12);
            __syncthreads();
#pragma unroll
            for (int kk = 0; kk < BK; ++kk) {
                float4 av  = *(const float4*)&xs[kk][ty * 4];
                float4 bv0 = *(const float4*)&ws[kk][tx * 8];
                float4 bv1 = *(const float4*)&ws[kk][tx * 8 + 4];
                float ar[4] = {av.x, av.y, av.z, av.w};
                float br[8] = {bv0.x, bv0.y, bv0.z, bv0.w, bv1.x, bv1.y, bv1.z, bv1.w};
#pragma unroll
                for (int i = 0; i < 4; i++)
#pragma unroll
                    for (int j = 0; j < 8; j++) c[i][j] = fmaf(ar[i], br[j], c[i][j]);
            }
        }
        const int gcol = n0 + tx * 8;
        float4 bb0 = *(const float4*)(b2 + (size_t)e * DN + gcol);
        float4 bb1 = *(const float4*)(b2 + (size_t)e * DN + gcol + 4);
        const float brr[8] = {bb0.x, bb0.y, bb0.z, bb0.w, bb1.x, bb1.y, bb1.z, bb1.w};
#pragma unroll
        for (int rr = 0; rr < 4; ++rr) {
            int id = rows[ty * 4 + rr];
            if (id >= 0) {
                float v[8];
#pragma unroll
                for (int j = 0; j < 8; j++) v[j] = c[rr][j] + brr[j];
                float4* dst = (float4*)(g_y + (size_t)id * DN + gcol);
                dst[0] = make_float4(v[0], v[1], v[2], v[3]);
                dst[1] = make_float4(v[4], v[5], v[6], v[7]);
            }
        }
    }
}

// ---------------- 5: combine + residual + final LN --------------------------
__global__ __launch_bounds__(256) void final_kernel(const float* __restrict__ x,
                                                    const float* __restrict__ ln_g,
                                                    const float* __restrict__ ln_b,
                                                    float* __restrict__ out) {
    const int t = blockIdx.x;
    __shared__ __align__(16) float s[DN];
    __shared__ float red[2][8];
    const float w0 = g_wk[2 * t], w1v = g_wk[2 * t + 1];
    const float* y0 = g_y + (size_t)(2 * t) * DN;
    const float* y1 = g_y + (size_t)(2 * t + 1) * DN;
    const float* xr = x + (size_t)t * DN;
    float ls = 0.f, lq = 0.f;
    for (int i = threadIdx.x; i < DN; i += blockDim.x) {
        float v = xr[i] + w0 * y0[i] + w1v * y1[i];
        s[i] = v; ls += v; lq += v * v;
    }
    int lane = threadIdx.x & 31, wid = threadIdx.x >> 5;
    for (int off = 16; off; off >>= 1) {
        ls += __shfl_down_sync(0xffffffffu, ls, off);
        lq += __shfl_down_sync(0xffffffffu, lq, off);
    }
    if (lane == 0) { red[0][wid] = ls; red[1][wid] = lq; }
    __syncthreads();
    if (wid == 0) {
        ls = (lane < 8) ? red[0][lane] : 0.f;
        lq = (lane < 8) ? red[1][lane] : 0.f;
        for (int off = 4; off; off >>= 1) {
            ls += __shfl_down_sync(0xffffffffu, ls, off);
            lq += __shfl_down_sync(0xffffffffu, lq, off);
        }
        if (lane == 0) { red[0][0] = ls; red[1][0] = lq; }
    }
    __syncthreads();
    float mean = red[0][0] * (1.f / DN);
    float var  = red[1][0] * (1.f / DN) - mean * mean;
    float rstd = rsqrtf(var + EPSV);
    for (int i = threadIdx.x; i < DN; i += blockDim.x)
        out[(size_t)t * DN + i] = (s[i] - mean) * rstd * ln_g[i] + ln_b[i];
}

// ---------------- launch ----------------------------------------------------
extern "C" void kernel_launch(void* const* d_in, const int* in_sizes, int n_in,
                              void* d_out, int out_size) {
    const float* x      = (const float*)d_in[0];
    const float* gate_w = (const float*)d_in[1];
    const float* w1     = (const float*)d_in[2];
    const float* b1     = (const float*)d_in[3];
    const float* ln1_g  = (const float*)d_in[4];
    const float* ln1_b  = (const float*)d_in[5];
    const float* w2     = (const float*)d_in[6];
    const float* b2     = (const float*)d_in[7];
    const float* ln_g   = (const float*)d_in[8];
    const float* ln_b   = (const float*)d_in[9];
    float* out = (float*)d_out;

    zero_kernel<<<64, 256>>>();
    gate_kernel<<<TT / 8, 256>>>(x, gate_w);
    ffn1_kernel<<<dim3(TT / TM, NE, 2), NTH>>>(x, w1, b1);
    act_kernel<<<TT * 2, 256>>>(ln1_g, ln1_b);
    ffn2_kernel<<<dim3(TT / TM, NE, 2), NTH>>>(w2, b2);
    final_kernel<<<TT, 256>>>(x, ln_g, ln_b, out);
}

// round 2
// speedup vs baseline: 6.5337x; 6.5337x over previous
#include <cuda_runtime.h>
#include <math.h>

#define TT   4096      // tokens
#define DN   1024      // model dim
#define HN   2048      // hidden dim
#define NE   8         // experts
#define EPSV 1e-5f

#define TMM  128       // block tile M
#define TNN  128       // block tile N
#define BKK  32        // k chunk

// ---------------- scratch (device globals; no allocation allowed) ----------
__device__ int   g_cnt[NE];
__device__ int   g_list[NE * TT];            // assignment ids grouped by expert
__device__ float g_wk[TT * 2];               // combine weight per assignment
__device__ unsigned char g_eid[TT * 2];      // expert id per assignment
__device__ float g_sums[TT * 2 * 2];         // per-assignment sum, sumsq over H
__device__ float g_h[(size_t)TT * 2 * HN];   // 64 MB: h (pre-LN -> post-gelu)
__device__ float g_y[(size_t)TT * 2 * DN];   // 32 MB: expert outputs

__device__ __forceinline__ unsigned f2tf(float f) {
    unsigned u; asm("cvt.rna.tf32.f32 %0, %1;" : "=r"(u) : "f"(f)); return u;
}
__device__ __forceinline__ void mma8(float c[4], const unsigned a[4], const unsigned b[2]) {
    asm("mma.sync.aligned.m16n8k8.row.col.f32.tf32.tf32.f32 "
        "{%0,%1,%2,%3},{%4,%5,%6,%7},{%8,%9},{%0,%1,%2,%3};"
        : "+f"(c[0]), "+f"(c[1]), "+f"(c[2]), "+f"(c[3])
        : "r"(a[0]), "r"(a[1]), "r"(a[2]), "r"(a[3]), "r"(b[0]), "r"(b[1]));
}

// ---------------- 0: zero counters/stats -----------------------------------
__global__ void zero_kernel() {
    int tid = blockIdx.x * blockDim.x + threadIdx.x;
    if (tid < NE) g_cnt[tid] = 0;
    for (int i = tid; i < TT * 2 * 2; i += gridDim.x * blockDim.x) g_sums[i] = 0.f;
}

// ---------------- 1: gating (one warp per token) ----------------------------
__global__ __launch_bounds__(256) void gate_kernel(const float* __restrict__ x,
                                                   const float* __restrict__ gw) {
    int t = blockIdx.x * 8 + (threadIdx.x >> 5);
    if (t >= TT) return;
    int lane = threadIdx.x & 31;
    float acc[NE];
#pragma unroll
    for (int e = 0; e < NE; e++) acc[e] = 0.f;
    const float* xr = x + (size_t)t * DN;
    for (int i = lane; i < DN; i += 32) {
        float xv = xr[i];
        const float4 ga = *(const float4*)(gw + (size_t)i * NE);
        const float4 gb = *(const float4*)(gw + (size_t)i * NE + 4);
        acc[0] = fmaf(xv, ga.x, acc[0]); acc[1] = fmaf(xv, ga.y, acc[1]);
        acc[2] = fmaf(xv, ga.z, acc[2]); acc[3] = fmaf(xv, ga.w, acc[3]);
        acc[4] = fmaf(xv, gb.x, acc[4]); acc[5] = fmaf(xv, gb.y, acc[5]);
        acc[6] = fmaf(xv, gb.z, acc[6]); acc[7] = fmaf(xv, gb.w, acc[7]);
    }
#pragma unroll
    for (int e = 0; e < NE; e++)
        for (int off = 16; off; off >>= 1)
            acc[e] += __shfl_xor_sync(0xffffffffu, acc[e], off);
    if (lane == 0) {
        int i0 = 0; float v0 = acc[0];
#pragma unroll
        for (int e = 1; e < NE; e++) if (acc[e] > v0) { v0 = acc[e]; i0 = e; }
        int i1 = -1; float v1 = -1e30f;
#pragma unroll
        for (int e = 0; e < NE; e++) if (e != i0 && acc[e] > v1) { v1 = acc[e]; i1 = e; }
        float ee = __expf(v1 - v0);
        float w0 = 1.f / (1.f + ee);
        float w1 = ee / (1.f + ee);
        int id0 = t * 2, id1 = t * 2 + 1;
        g_wk[id0] = w0; g_wk[id1] = w1;
        g_eid[id0] = (unsigned char)i0; g_eid[id1] = (unsigned char)i1;
        int s0 = atomicAdd(&g_cnt[i0], 1); g_list[i0 * TT + s0] = id0;
        int s1 = atomicAdd(&g_cnt[i1], 1); g_list[i1 * TT + s1] = id1;
    }
}

// ---------------- 2: ffn1  h = x @ w1[e] + b1  (tf32 mma, + row stats) ------
__global__ __launch_bounds__(256) void ffn1_mma(const float* __restrict__ x,
                                                const float* __restrict__ w1,
                                                const float* __restrict__ b1) {
    const int e = blockIdx.y;
    const int cnt = g_cnt[e];
    const int rowbase = blockIdx.x * TMM;
    if (rowbase >= cnt) return;
    const int n0 = blockIdx.z * TNN;

    __shared__ unsigned As[TMM][BKK + 4];    // [m][k] stride 36 -> conflict-free frags
    __shared__ unsigned Bs[BKK][TNN + 8];    // [k][n] stride 136 -> conflict-free frags
    __shared__ int rows[TMM];

    const int tid = threadIdx.x;
    if (tid < TMM) {
        int r = rowbase + tid;
        rows[tid] = (r < cnt) ? g_list[e * TT + r] : -1;
    }
    __syncthreads();

    // loader mapping: A: 4 float4 per thread; B: 4 float4 per thread
    const int ar = tid >> 3;            // A row base 0..31 (+32*i)
    const int ak = (tid & 7) * 4;       // A k offset
    const int bk = tid >> 5;            // B k base 0..7 (+8*i)
    const int bn = (tid & 31) * 4;      // B n offset
    const float* aptr[4];
    int arid[4];
#pragma unroll
    for (int i = 0; i < 4; i++) {
        int id = rows[ar + 32 * i];
        arid[i] = id;
        aptr[i] = x + (size_t)((id < 0) ? 0 : (id >> 1)) * DN + ak;
    }
    const float* bptr = w1 + (size_t)e * DN * HN + n0 + bn;

    const int lane = tid & 31;
    const int wid = tid >> 5;
    const int wm = (wid >> 1) * 32;     // 4 warps along M
    const int wn = (wid & 1) * 64;      // 2 warps along N
    const int g = lane >> 2, t4 = lane & 3;

    float c[2][8][4];
#pragma unroll
    for (int mt = 0; mt < 2; mt++)
#pragma unroll
        for (int nt = 0; nt < 8; nt++)
#pragma unroll
            for (int r = 0; r < 4; r++) c[mt][nt][r] = 0.f;

    float4 pa[4], pb[4];
#pragma unroll
    for (int i = 0; i < 4; i++) pa[i] = *(const float4*)(aptr[i]);
#pragma unroll
    for (int i = 0; i < 4; i++) pb[i] = *(const float4*)(bptr + (size_t)(bk + 8 * i) * HN);

    for (int k0 = 0; k0 < DN; k0 += BKK) {
#pragma unroll
        for (int i = 0; i < 4; i++) {
            *(uint4*)&As[ar + 32 * i][ak] =
                make_uint4(f2tf(pa[i].x), f2tf(pa[i].y), f2tf(pa[i].z), f2tf(pa[i].w));
            *(uint4*)&Bs[bk + 8 * i][bn] =
                make_uint4(f2tf(pb[i].x), f2tf(pb[i].y), f2tf(pb[i].z), f2tf(pb[i].w));
        }
        __syncthreads();
        if (k0 + BKK < DN) {
#pragma unroll
            for (int i = 0; i < 4; i++) pa[i] = *(const float4*)(aptr[i] + k0 + BKK);
#pragma unroll
            for (int i = 0; i < 4; i++)
                pb[i] = *(const float4*)(bptr + (size_t)(k0 + BKK + bk + 8 * i) * HN);
        }
#pragma unroll
        for (int ks = 0; ks < 4; ks++) {
            const int kk = ks * 8;
            unsigned af[2][4], bf[8][2];
#pragma unroll
            for (int mt = 0; mt < 2; mt++) {
                int rb = wm + mt * 16;
                af[mt][0] = As[rb + g][kk + t4];
                af[mt][1] = As[rb + g + 8][kk + t4];
                af[mt][2] = As[rb + g][kk + t4 + 4];
                af[mt][3] = As[rb + g + 8][kk + t4 + 4];
            }
#pragma unroll
            for (int nt = 0; nt < 8; nt++) {
                int col = wn + nt * 8 + g;
                bf[nt][0] = Bs[kk + t4][col];
                bf[nt][1] = Bs[kk + t4 + 4][col];
            }
#pragma unroll
            for (int mt = 0; mt < 2; mt++)
#pragma unroll
                for (int nt = 0; nt < 8; nt++) mma8(c[mt][nt], af[mt], bf[nt]);
        }
        __syncthreads();
    }

    // epilogue: bias, store h, per-row stats
    const float* be = b1 + (size_t)e * HN + n0;
#pragma unroll
    for (int mt = 0; mt < 2; mt++) {
        int r0l = wm + mt * 16 + g;
        int r1l = r0l + 8;
        int id0 = rows[r0l], id1 = rows[r1l];
        float s0 = 0.f, q0 = 0.f, s1 = 0.f, q1 = 0.f;
#pragma unroll
        for (int nt = 0; nt < 8; nt++) {
            int col = wn + nt * 8 + 2 * t4;
            float bx = be[col], by = be[col + 1];
            float v00 = c[mt][nt][0] + bx, v01 = c[mt][nt][1] + by;
            float v10 = c[mt][nt][2] + bx, v11 = c[mt][nt][3] + by;
            s0 += v00 + v01; q0 += v00 * v00 + v01 * v01;
            s1 += v10 + v11; q1 += v10 * v10 + v11 * v11;
            if (id0 >= 0)
                *(float2*)(g_h + (size_t)id0 * HN + n0 + col) = make_float2(v00, v01);
            if (id1 >= 0)
                *(float2*)(g_h + (size_t)id1 * HN + n0 + col) = make_float2(v10, v11);
        }
#pragma unroll
        for (int off = 1; off <= 2; off <<= 1) {
            s0 += __shfl_xor_sync(0xffffffffu, s0, off);
            q0 += __shfl_xor_sync(0xffffffffu, q0, off);
            s1 += __shfl_xor_sync(0xffffffffu, s1, off);
            q1 += __shfl_xor_sync(0xffffffffu, q1, off);
        }
        if (t4 == 0) {
            if (id0 >= 0) { atomicAdd(&g_sums[2 * id0], s0); atomicAdd(&g_sums[2 * id0 + 1], q0); }
            if (id1 >= 0) { atomicAdd(&g_sums[2 * id1], s1); atomicAdd(&g_sums[2 * id1 + 1], q1); }
        }
    }
}

// ---------------- 3: LN1 + exact GeLU in place ------------------------------
__global__ __launch_bounds__(256) void act_kernel(const float* __restrict__ ln1_g,
                                                  const float* __restrict__ ln1_b) {
    const int id = blockIdx.x;
    const int e  = g_eid[id];
    float sum  = g_sums[2 * id], sq = g_sums[2 * id + 1];
    float mean = sum * (1.f / HN);
    float var  = sq * (1.f / HN) - mean * mean;
    float rstd = rsqrtf(var + EPSV);
    float* hr = g_h + (size_t)id * HN;
    const float* gg = ln1_g + (size_t)e * HN;
    const float* bb = ln1_b + (size_t)e * HN;
    for (int i = threadIdx.x; i < HN; i += blockDim.x) {
        float v = (hr[i] - mean) * rstd * gg[i] + bb[i];
        hr[i] = v * normcdff(v);     // exact gelu
    }
}

// ---------------- 4: ffn2  y = h @ w2[e] + b2  (tf32 mma) -------------------
__global__ __launch_bounds__(256) void ffn2_mma(const float* __restrict__ w2,
                                                const float* __restrict__ b2) {
    const int e = blockIdx.y;
    const int cnt = g_cnt[e];
    const int rowbase = blockIdx.x * TMM;
    if (rowbase >= cnt) return;
    const int n0 = blockIdx.z * TNN;

    __shared__ unsigned As[TMM][BKK + 4];
    __shared__ unsigned Bs[BKK][TNN + 8];
    __shared__ int rows[TMM];

    const int tid = threadIdx.x;
    if (tid < TMM) {
        int r = rowbase + tid;
        rows[tid] = (r < cnt) ? g_list[e * TT + r] : -1;
    }
    __syncthreads();

    const int ar = tid >> 3;
    const int ak = (tid & 7) * 4;
    const int bk = tid >> 5;
    const int bn = (tid & 31) * 4;
    const float* aptr[4];
#pragma unroll
    for (int i = 0; i < 4; i++) {
        int id = rows[ar + 32 * i];
        aptr[i] = g_h + (size_t)((id < 0) ? 0 : id) * HN + ak;
    }
    const float* bptr = w2 + (size_t)e * HN * DN + n0 + bn;

    const int lane = tid & 31;
    const int wid = tid >> 5;
    const int wm = (wid >> 1) * 32;
    const int wn = (wid & 1) * 64;
    const int g = lane >> 2, t4 = lane & 3;

    float c[2][8][4];
#pragma unroll
    for (int mt = 0; mt < 2; mt++)
#pragma unroll
        for (int nt = 0; nt < 8; nt++)
#pragma unroll
            for (int r = 0; r < 4; r++) c[mt][nt][r] = 0.f;

    float4 pa[4], pb[4];
#pragma unroll
    for (int i = 0; i < 4; i++) pa[i] = *(const float4*)(aptr[i]);
#pragma unroll
    for (int i = 0; i < 4; i++) pb[i] = *(const float4*)(bptr + (size_t)(bk + 8 * i) * DN);

    for (int k0 = 0; k0 < HN; k0 += BKK) {
#pragma unroll
        for (int i = 0; i < 4; i++) {
            *(uint4*)&As[ar + 32 * i][ak] =
                make_uint4(f2tf(pa[i].x), f2tf(pa[i].y), f2tf(pa[i].z), f2tf(pa[i].w));
            *(uint4*)&Bs[bk + 8 * i][bn] =
                make_uint4(f2tf(pb[i].x), f2tf(pb[i].y), f2tf(pb[i].z), f2tf(pb[i].w));
        }
        __syncthreads();
        if (k0 + BKK < HN) {
#pragma unroll
            for (int i = 0; i < 4; i++) pa[i] = *(const float4*)(aptr[i] + k0 + BKK);
#pragma unroll
            for (int i = 0; i < 4; i++)
                pb[i] = *(const float4*)(bptr + (size_t)(k0 + BKK + bk + 8 * i) * DN);
        }
#pragma unroll
        for (int ks = 0; ks < 4; ks++) {
            const int kk = ks * 8;
            unsigned af[2][4], bf[8][2];
#pragma unroll
            for (int mt = 0; mt < 2; mt++) {
                int rb = wm + mt * 16;
                af[mt][0] = As[rb + g][kk + t4];
                af[mt][1] = As[rb + g + 8][kk + t4];
                af[mt][2] = As[rb + g][kk + t4 + 4];
                af[mt][3] = As[rb + g + 8][kk + t4 + 4];
            }
#pragma unroll
            for (int nt = 0; nt < 8; nt++) {
                int col = wn + nt * 8 + g;
                bf[nt][0] = Bs[kk + t4][col];
                bf[nt][1] = Bs[kk + t4 + 4][col];
            }
#pragma unroll
            for (int mt = 0; mt < 2; mt++)
#pragma unroll
                for (int nt = 0; nt < 8; nt++) mma8(c[mt][nt], af[mt], bf[nt]);
        }
        __syncthreads();
    }

    const float* be = b2 + (size_t)e * DN + n0;
#pragma unroll
    for (int mt = 0; mt < 2; mt++) {
        int r0l = wm + mt * 16 + g;
        int r1l = r0l + 8;
        int id0 = rows[r0l], id1 = rows[r1l];
#pragma unroll
        for (int nt = 0; nt < 8; nt++) {
            int col = wn + nt * 8 + 2 * t4;
            float bx = be[col], by = be[col + 1];
            if (id0 >= 0)
                *(float2*)(g_y + (size_t)id0 * DN + n0 + col) =
                    make_float2(c[mt][nt][0] + bx, c[mt][nt][1] + by);
            if (id1 >= 0)
                *(float2*)(g_y + (size_t)id1 * DN + n0 + col) =
                    make_float2(c[mt][nt][2] + bx, c[mt][nt][3] + by);
        }
    }
}

// ---------------- 5: combine + residual + final LN --------------------------
__global__ __launch_bounds__(256) void final_kernel(const float* __restrict__ x,
                                                    const float* __restrict__ ln_g,
                                                    const float* __restrict__ ln_b,
                                                    float* __restrict__ out) {
    const int t = blockIdx.x;
    __shared__ __align__(16) float s[DN];
    __shared__ float red[2][8];
    const float w0 = g_wk[2 * t], w1v = g_wk[2 * t + 1];
    const float* y0 = g_y + (size_t)(2 * t) * DN;
    const float* y1 = g_y + (size_t)(2 * t + 1) * DN;
    const float* xr = x + (size_t)t * DN;
    float ls = 0.f, lq = 0.f;
    for (int i = threadIdx.x; i < DN; i += blockDim.x) {
        float v = xr[i] + w0 * y0[i] + w1v * y1[i];
        s[i] = v; ls += v; lq += v * v;
    }
    int lane = threadIdx.x & 31, wid = threadIdx.x >> 5;
    for (int off = 16; off; off >>= 1) {
        ls += __shfl_down_sync(0xffffffffu, ls, off);
        lq += __shfl_down_sync(0xffffffffu, lq, off);
    }
    if (lane == 0) { red[0][wid] = ls; red[1][wid] = lq; }
    __syncthreads();
    if (wid == 0) {
        ls = (lane < 8) ? red[0][lane] : 0.f;
        lq = (lane < 8) ? red[1][lane] : 0.f;
        for (int off = 4; off; off >>= 1) {
            ls += __shfl_down_sync(0xffffffffu, ls, off);
            lq += __shfl_down_sync(0xffffffffu, lq, off);
        }
        if (lane == 0) { red[0][0] = ls; red[1][0] = lq; }
    }
    __syncthreads();
    float mean = red[0][0] * (1.f / DN);
    float var  = red[1][0] * (1.f / DN) - mean * mean;
    float rstd = rsqrtf(var + EPSV);
    for (int i = threadIdx.x; i < DN; i += blockDim.x)
        out[(size_t)t * DN + i] = (s[i] - mean) * rstd * ln_g[i] + ln_b[i];
}

// ---------------- launch ----------------------------------------------------
extern "C" void kernel_launch(void* const* d_in, const int* in_sizes, int n_in,
                              void* d_out, int out_size) {
    const float* x      = (const float*)d_in[0];
    const float* gate_w = (const float*)d_in[1];
    const float* w1     = (const float*)d_in[2];
    const float* b1     = (const float*)d_in[3];
    const float* ln1_g  = (const float*)d_in[4];
    const float* ln1_b  = (const float*)d_in[5];
    const float* w2     = (const float*)d_in[6];
    const float* b2     = (const float*)d_in[7];
    const float* ln_g   = (const float*)d_in[8];
    const float* ln_b   = (const float*)d_in[9];
    float* out = (float*)d_out;

    zero_kernel<<<64, 256>>>();
    gate_kernel<<<TT / 8, 256>>>(x, gate_w);
    ffn1_mma<<<dim3(TT / TMM, NE, HN / TNN), 256>>>(x, w1, b1);
    act_kernel<<<TT * 2, 256>>>(ln1_g, ln1_b);
    ffn2_mma<<<dim3(TT / TMM, NE, DN / TNN), 256>>>(w2, b2);
    final_kernel<<<TT, 256>>>(x, ln_g, ln_b, out);
}

// round 5
// speedup vs baseline: 9.4703x; 1.4494x over previous
#include <cuda_runtime.h>
#include <cuda_fp16.h>
#include <cstdint>
#include <math.h>

#define TT   4096
#define DN   1024
#define HN   2048
#define NE   8
#define EPSV 1e-5f

#define TMM  128       // block tile M
#define TNN  128       // block tile N
#define BKK  32        // k chunk (halfs)

#define ASTRIDE 40     // As row stride in halfs (16*2.5 -> conflict-free ldmatrix)
#define BSTRIDE 264    // Bs row stride in halfs

// ---------------- scratch ----------------------------------------------------
__device__ int   g_cnt[NE];
__device__ int   g_list[NE * TT];
__device__ float g_wk[TT * 2];
__device__ unsigned char g_eid[TT * 2];
__device__ float g_sums[TT * 2 * 2];
__device__ float g_h[(size_t)TT * 2 * HN];
__device__ float g_y[(size_t)TT * 2 * DN];

// ---------------- helpers ----------------------------------------------------
__device__ __forceinline__ uint32_t f2h2(float lo, float hi) {
    uint32_t r;
    asm("cvt.rn.f16x2.f32 %0, %1, %2;" : "=r"(r) : "f"(hi), "f"(lo));
    return r;
}
__device__ __forceinline__ uint32_t smem_u32(const void* p) {
    uint32_t a;
    asm("{ .reg .u64 t; cvta.to.shared.u64 t, %1; cvt.u32.u64 %0, t; }" : "=r"(a) : "l"(p));
    return a;
}
__device__ __forceinline__ void ldsm4(uint32_t& r0, uint32_t& r1, uint32_t& r2, uint32_t& r3,
                                      uint32_t addr) {
    asm volatile("ldmatrix.sync.aligned.m8n8.x4.shared.b16 {%0,%1,%2,%3}, [%4];"
                 : "=r"(r0), "=r"(r1), "=r"(r2), "=r"(r3) : "r"(addr));
}
__device__ __forceinline__ void ldsm4t(uint32_t& r0, uint32_t& r1, uint32_t& r2, uint32_t& r3,
                                       uint32_t addr) {
    asm volatile("ldmatrix.sync.aligned.m8n8.x4.trans.shared.b16 {%0,%1,%2,%3}, [%4];"
                 : "=r"(r0), "=r"(r1), "=r"(r2), "=r"(r3) : "r"(addr));
}
__device__ __forceinline__ void mma16(float c[4], const uint32_t a[4], const uint32_t b0,
                                      const uint32_t b1) {
    asm("mma.sync.aligned.m16n8k16.row.col.f32.f16.f16.f32 "
        "{%0,%1,%2,%3},{%4,%5,%6,%7},{%8,%9},{%0,%1,%2,%3};"
        : "+f"(c[0]), "+f"(c[1]), "+f"(c[2]), "+f"(c[3])
        : "r"(a[0]), "r"(a[1]), "r"(a[2]), "r"(a[3]), "r"(b0), "r"(b1));
}

// ---------------- 0: zero ----------------------------------------------------
__global__ void zero_kernel() {
    int tid = blockIdx.x * blockDim.x + threadIdx.x;
    if (tid < NE) g_cnt[tid] = 0;
    for (int i = tid; i < TT * 2 * 2; i += gridDim.x * blockDim.x) g_sums[i] = 0.f;
}

// ---------------- 1: gating --------------------------------------------------
__global__ __launch_bounds__(256) void gate_kernel(const float* __restrict__ x,
                                                   const float* __restrict__ gw) {
    int t = blockIdx.x * 8 + (threadIdx.x >> 5);
    if (t >= TT) return;
    int lane = threadIdx.x & 31;
    float acc[NE];
#pragma unroll
    for (int e = 0; e < NE; e++) acc[e] = 0.f;
    const float* xr = x + (size_t)t * DN;
    for (int i = lane; i < DN; i += 32) {
        float xv = xr[i];
        const float4 ga = *(const float4*)(gw + (size_t)i * NE);
        const float4 gb = *(const float4*)(gw + (size_t)i * NE + 4);
        acc[0] = fmaf(xv, ga.x, acc[0]); acc[1] = fmaf(xv, ga.y, acc[1]);
        acc[2] = fmaf(xv, ga.z, acc[2]); acc[3] = fmaf(xv, ga.w, acc[3]);
        acc[4] = fmaf(xv, gb.x, acc[4]); acc[5] = fmaf(xv, gb.y, acc[5]);
        acc[6] = fmaf(xv, gb.z, acc[6]); acc[7] = fmaf(xv, gb.w, acc[7]);
    }
#pragma unroll
    for (int e = 0; e < NE; e++)
        for (int off = 16; off; off >>= 1)
            acc[e] += __shfl_xor_sync(0xffffffffu, acc[e], off);
    if (lane == 0) {
        int i0 = 0; float v0 = acc[0];
#pragma unroll
        for (int e = 1; e < NE; e++) if (acc[e] > v0) { v0 = acc[e]; i0 = e; }
        int i1 = -1; float v1 = -1e30f;
#pragma unroll
        for (int e = 0; e < NE; e++) if (e != i0 && acc[e] > v1) { v1 = acc[e]; i1 = e; }
        float ee = __expf(v1 - v0);
        float w0 = 1.f / (1.f + ee);
        float w1 = ee / (1.f + ee);
        int id0 = t * 2, id1 = t * 2 + 1;
        g_wk[id0] = w0; g_wk[id1] = w1;
        g_eid[id0] = (unsigned char)i0; g_eid[id1] = (unsigned char)i1;
        int s0 = atomicAdd(&g_cnt[i0], 1); g_list[i0 * TT + s0] = id0;
        int s1 = atomicAdd(&g_cnt[i1], 1); g_list[i1 * TT + s1] = id1;
    }
}

// ---------------- fp16 mma grouped GEMM --------------------------------------
// FIRST: A = x[token], Out = g_h (+stats).  !FIRST: A = g_h, Out = g_y.
template <int KDIM, int LDN, bool FIRST>
__global__ __launch_bounds__(256) void moe_gemm_h(const float* __restrict__ Araw,
                                                  const float* __restrict__ W,
                                                  const float* __restrict__ Bias) {
    const int e = blockIdx.y;
    const int cnt = g_cnt[e];
    const int rowbase = blockIdx.x * TMM;
    if (rowbase >= cnt) return;
    const int n0 = blockIdx.z * TNN;

    __shared__ __align__(16) __half As[TMM][ASTRIDE];
    __shared__ __align__(16) __half Bs[BKK][BSTRIDE];
    __shared__ int rows_s[TMM];

    const int tid = threadIdx.x;
    if (tid < TMM) {
        int r = rowbase + tid;
        rows_s[tid] = (r < cnt) ? g_list[e * TT + r] : -1;
    }
    __syncthreads();

    const float* Abase = FIRST ? Araw : (const float*)g_h;
    float* Outp = FIRST ? (float*)g_h : (float*)g_y;

    // ---- staging maps ----
    // A: thread loads 4 rows (rb + 32i), 4 consecutive k at q*4
    const int q = tid & 7, rb = tid >> 3;
    const float* aptr[4];
#pragma unroll
    for (int i = 0; i < 4; i++) {
        int id = rows_s[rb + 32 * i];
        int r = (id < 0) ? 0 : (FIRST ? (id >> 1) : id);
        aptr[i] = Abase + (size_t)r * KDIM + q * 4;
    }
    // B: thread loads row k = tid>>3, 16 consecutive n at (tid&7)*16
    const int bkr = tid >> 3;
    const int bnc = (tid & 7) * 16;
    const float* bptr = W + (size_t)e * KDIM * LDN + (size_t)bkr * LDN + n0 + bnc;

    const int lane = tid & 31;
    const int wid = tid >> 5;
    const int wm = (wid >> 1) * 32;
    const int wn = (wid & 1) * 64;
    const int g = lane >> 2, t4 = lane & 3;

    const uint32_t as_b = smem_u32(&As[0][0]);
    const uint32_t bs_b = smem_u32(&Bs[0][0]);
    // ldmatrix A address pieces: row = wm + mt*16 + (lane&15), koff = (lane>=16)*8
    const uint32_t a_addr0 = as_b + ((wm + (lane & 15)) * ASTRIDE + ((lane >> 4) << 3)) * 2;
    // ldmatrix B (trans): row = kc + (lane&7) + ((lane&8)?8:0), col = wn + np*16 + ((lane&16)?8:0)
    const uint32_t b_addr0 = bs_b + (((lane & 7) + ((lane & 8) ? 8 : 0)) * BSTRIDE +
                                     wn + ((lane & 16) ? 8 : 0)) * 2;

    float c[2][8][4];
#pragma unroll
    for (int mt = 0; mt < 2; mt++)
#pragma unroll
        for (int nt = 0; nt < 8; nt++)
#pragma unroll
            for (int r = 0; r < 4; r++) c[mt][nt][r] = 0.f;

    float4 pa[4], pb[4];
#pragma unroll
    for (int i = 0; i < 4; i++) pa[i] = *(const float4*)(aptr[i]);
#pragma unroll
    for (int i = 0; i < 4; i++) pb[i] = *(const float4*)(bptr + 4 * i);

    const int NK = KDIM / BKK;
    for (int ch = 0; ch < NK; ++ch) {
        __syncthreads();   // previous mma done reading smem
        // ---- STS chunk ch ----
#pragma unroll
        for (int i = 0; i < 4; i++) {
            uint32_t lo = f2h2(pa[i].x, pa[i].y);
            uint32_t hi = f2h2(pa[i].z, pa[i].w);
            *(uint2*)&As[rb + 32 * i][q * 4] = make_uint2(lo, hi);
        }
        {
            uint4 v0 = make_uint4(f2h2(pb[0].x, pb[0].y), f2h2(pb[0].z, pb[0].w),
                                  f2h2(pb[1].x, pb[1].y), f2h2(pb[1].z, pb[1].w));
            uint4 v1 = make_uint4(f2h2(pb[2].x, pb[2].y), f2h2(pb[2].z, pb[2].w),
                                  f2h2(pb[3].x, pb[3].y), f2h2(pb[3].z, pb[3].w));
            *(uint4*)&Bs[bkr][bnc] = v0;
            *(uint4*)&Bs[bkr][bnc + 8] = v1;
        }
        __syncthreads();
        // ---- prefetch next chunk ----
        if (ch + 1 < NK) {
            const int k0 = (ch + 1) * BKK;
#pragma unroll
            for (int i = 0; i < 4; i++) pa[i] = *(const float4*)(aptr[i] + k0);
            const float* bp = bptr + (size_t)k0 * LDN;
#pragma unroll
            for (int i = 0; i < 4; i++) pb[i] = *(const float4*)(bp + 4 * i);
        }
        // ---- 2 x k16 mma steps ----
#pragma unroll
        for (int ks = 0; ks < 2; ks++) {
            const int kc = ks * 16;
            uint32_t af[2][4];
#pragma unroll
            for (int mt = 0; mt < 2; mt++)
                ldsm4(af[mt][0], af[mt][1], af[mt][2], af[mt][3],
                      a_addr0 + (mt * 16 * ASTRIDE + kc) * 2);
            uint32_t bf[8][2];
#pragma unroll
            for (int np = 0; np < 4; np++) {
                uint32_t r0, r1, r2, r3;
                ldsm4t(r0, r1, r2, r3, b_addr0 + (kc * BSTRIDE + np * 16) * 2);
                bf[2 * np][0] = r0; bf[2 * np][1] = r1;
                bf[2 * np + 1][0] = r2; bf[2 * np + 1][1] = r3;
            }
#pragma unroll
            for (int mt = 0; mt < 2; mt++)
#pragma unroll
                for (int nt = 0; nt < 8; nt++)
                    mma16(c[mt][nt], af[mt], bf[nt][0], bf[nt][1]);
        }
    }

    // ---- epilogue ----
    const float* be = Bias + (size_t)e * LDN + n0;
#pragma unroll
    for (int mt = 0; mt < 2; mt++) {
        int r0l = wm + mt * 16 + g;
        int r1l = r0l + 8;
        int id0 = rows_s[r0l], id1 = rows_s[r1l];
        float s0 = 0.f, q0 = 0.f, s1 = 0.f, q1 = 0.f;
#pragma unroll
        for (int nt = 0; nt < 8; nt++) {
            int col = wn + nt * 8 + 2 * t4;
            float bx = be[col], by = be[col + 1];
            float v00 = c[mt][nt][0] + bx, v01 = c[mt][nt][1] + by;
            float v10 = c[mt][nt][2] + bx, v11 = c[mt][nt][3] + by;
            if (FIRST) {
                s0 += v00 + v01; q0 += v00 * v00 + v01 * v01;
                s1 += v10 + v11; q1 += v10 * v10 + v11 * v11;
            }
            if (id0 >= 0)
                *(float2*)(Outp + (size_t)id0 * LDN + n0 + col) = make_float2(v00, v01);
            if (id1 >= 0)
                *(float2*)(Outp + (size_t)id1 * LDN + n0 + col) = make_float2(v10, v11);
        }
        if (FIRST) {
#pragma unroll
            for (int off = 1; off <= 2; off <<= 1) {
                s0 += __shfl_xor_sync(0xffffffffu, s0, off);
                q0 += __shfl_xor_sync(0xffffffffu, q0, off);
                s1 += __shfl_xor_sync(0xffffffffu, s1, off);
                q1 += __shfl_xor_sync(0xffffffffu, q1, off);
            }
            if (t4 == 0) {
                if (id0 >= 0) { atomicAdd(&g_sums[2 * id0], s0); atomicAdd(&g_sums[2 * id0 + 1], q0); }
                if (id1 >= 0) { atomicAdd(&g_sums[2 * id1], s1); atomicAdd(&g_sums[2 * id1 + 1], q1); }
            }
        }
    }
}

// ---------------- 3: LN1 + exact GeLU ---------------------------------------
__global__ __launch_bounds__(256) void act_kernel(const float* __restrict__ ln1_g,
                                                  const float* __restrict__ ln1_b) {
    const int id = blockIdx.x;
    const int e = g_eid[id];
    float sum = g_sums[2 * id], sq = g_sums[2 * id + 1];
    float mean = sum * (1.f / HN);
    float var = sq * (1.f / HN) - mean * mean;
    float rstd = rsqrtf(var + EPSV);
    float4* hr = (float4*)(g_h + (size_t)id * HN);
    const float4* gg = (const float4*)(ln1_g + (size_t)e * HN);
    const float4* bb = (const float4*)(ln1_b + (size_t)e * HN);
    for (int i = threadIdx.x; i < HN / 4; i += blockDim.x) {
        float4 h4 = hr[i], g4 = gg[i], b4 = bb[i];
        float v;
        v = (h4.x - mean) * rstd * g4.x + b4.x; h4.x = v * normcdff(v);
        v = (h4.y - mean) * rstd * g4.y + b4.y; h4.y = v * normcdff(v);
        v = (h4.z - mean) * rstd * g4.z + b4.z; h4.z = v * normcdff(v);
        v = (h4.w - mean) * rstd * g4.w + b4.w; h4.w = v * normcdff(v);
        hr[i] = h4;
    }
}

// ---------------- 5: combine + residual + final LN ---------------------------
__global__ __launch_bounds__(256) void final_kernel(const float* __restrict__ x,
                                                    const float* __restrict__ ln_g,
                                                    const float* __restrict__ ln_b,
                                                    float* __restrict__ out) {
    const int t = blockIdx.x;
    __shared__ __align__(16) float s[DN];
    __shared__ float red[2][8];
    const float w0 = g_wk[2 * t], w1v = g_wk[2 * t + 1];
    const float* y0 = g_y + (size_t)(2 * t) * DN;
    const float* y1 = g_y + (size_t)(2 * t + 1) * DN;
    const float* xr = x + (size_t)t * DN;
    float ls = 0.f, lq = 0.f;
    for (int i = threadIdx.x; i < DN; i += blockDim.x) {
        float v = xr[i] + w0 * y0[i] + w1v * y1[i];
        s[i] = v; ls += v; lq += v * v;
    }
    int lane = threadIdx.x & 31, wid = threadIdx.x >> 5;
    for (int off = 16; off; off >>= 1) {
        ls += __shfl_down_sync(0xffffffffu, ls, off);
        lq += __shfl_down_sync(0xffffffffu, lq, off);
    }
    if (lane == 0) { red[0][wid] = ls; red[1][wid] = lq; }
    __syncthreads();
    if (wid == 0) {
        ls = (lane < 8) ? red[0][lane] : 0.f;
        lq = (lane < 8) ? red[1][lane] : 0.f;
        for (int off = 4; off; off >>= 1) {
            ls += __shfl_down_sync(0xffffffffu, ls, off);
            lq += __shfl_down_sync(0xffffffffu, lq, off);
        }
        if (lane == 0) { red[0][0] = ls; red[1][0] = lq; }
    }
    __syncthreads();
    float mean = red[0][0] * (1.f / DN);
    float var = red[1][0] * (1.f / DN) - mean * mean;
    float rstd = rsqrtf(var + EPSV);
    for (int i = threadIdx.x; i < DN; i += blockDim.x)
        out[(size_t)t * DN + i] = (s[i] - mean) * rstd * ln_g[i] + ln_b[i];
}

// ---------------- launch -----------------------------------------------------
extern "C" void kernel_launch(void* const* d_in, const int* in_sizes, int n_in,
                              void* d_out, int out_size) {
    const float* x      = (const float*)d_in[0];
    const float* gate_w = (const float*)d_in[1];
    const float* w1     = (const float*)d_in[2];
    const float* b1     = (const float*)d_in[3];
    const float* ln1_g  = (const float*)d_in[4];
    const float* ln1_b  = (const float*)d_in[5];
    const float* w2     = (const float*)d_in[6];
    const float* b2     = (const float*)d_in[7];
    const float* ln_g   = (const float*)d_in[8];
    const float* ln_b   = (const float*)d_in[9];
    float* out = (float*)d_out;

    zero_kernel<<<64, 256>>>();
    gate_kernel<<<TT / 8, 256>>>(x, gate_w);
    moe_gemm_h<DN, HN, true><<<dim3(TT / TMM, NE, HN / TNN), 256>>>(x, w1, b1);
    act_kernel<<<TT * 2, 256>>>(ln1_g, ln1_b);
    moe_gemm_h<HN, DN, false><<<dim3(TT / TMM, NE, DN / TNN), 256>>>(x, w2, b2);
    final_kernel<<<TT, 256>>>(x, ln_g, ln_b, out);
}

// round 8
// speedup vs baseline: 11.5436x; 1.2189x over previous
#include <cuda_runtime.h>
#include <cuda_fp16.h>
#include <cstdint>
#include <math.h>

#define TT   4096
#define DN   1024
#define HN   2048
#define NE   8
#define EPSV 1e-5f

#define TMM  128
#define TNN  128
#define BKK  32

#define ASTRIDE 40     // As row stride (halfs): 80B -> conflict-free ldmatrix
#define BSTRIDE 264    // Bs row stride (halfs): 528B -> conflict-free ldmatrix trans

// ---------------- scratch ----------------------------------------------------
__device__ int    g_cnt[NE];
__device__ int    g_list[NE * TT];
__device__ float  g_wk[TT * 2];
__device__ unsigned char g_eid[TT * 2];
__device__ float  g_sums[TT * 2 * 2];
__device__ __half g_h[(size_t)TT * 2 * HN];     // fp16 hidden
__device__ float  g_y[(size_t)TT * 2 * DN];     // fp32 expert outputs
__device__ __half g_w1h[(size_t)NE * DN * HN];  // fp16 weights
__device__ __half g_w2h[(size_t)NE * HN * DN];

// ---------------- helpers ----------------------------------------------------
__device__ __forceinline__ uint32_t f2h2(float lo, float hi) {
    uint32_t r;
    asm("cvt.rn.f16x2.f32 %0, %1, %2;" : "=r"(r) : "f"(hi), "f"(lo));
    return r;
}
__device__ __forceinline__ uint32_t smem_u32(const void* p) {
    uint32_t a;
    asm("{ .reg .u64 t; cvta.to.shared.u64 t, %1; cvt.u32.u64 %0, t; }" : "=r"(a) : "l"(p));
    return a;
}
__device__ __forceinline__ void ldsm4(uint32_t& r0, uint32_t& r1, uint32_t& r2, uint32_t& r3,
                                      uint32_t addr) {
    asm volatile("ldmatrix.sync.aligned.m8n8.x4.shared.b16 {%0,%1,%2,%3}, [%4];"
                 : "=r"(r0), "=r"(r1), "=r"(r2), "=r"(r3) : "r"(addr));
}
__device__ __forceinline__ void ldsm4t(uint32_t& r0, uint32_t& r1, uint32_t& r2, uint32_t& r3,
                                       uint32_t addr) {
    asm volatile("ldmatrix.sync.aligned.m8n8.x4.trans.shared.b16 {%0,%1,%2,%3}, [%4];"
                 : "=r"(r0), "=r"(r1), "=r"(r2), "=r"(r3) : "r"(addr));
}
__device__ __forceinline__ void mma16(float c[4], const uint32_t a[4], const uint32_t b0,
                                      const uint32_t b1) {
    asm("mma.sync.aligned.m16n8k16.row.col.f32.f16.f16.f32 "
        "{%0,%1,%2,%3},{%4,%5,%6,%7},{%8,%9},{%0,%1,%2,%3};"
        : "+f"(c[0]), "+f"(c[1]), "+f"(c[2]), "+f"(c[3])
        : "r"(a[0]), "r"(a[1]), "r"(a[2]), "r"(a[3]), "r"(b0), "r"(b1));
}

// ---------------- 0: zero ----------------------------------------------------
__global__ void zero_kernel() {
    int tid = blockIdx.x * blockDim.x + threadIdx.x;
    if (tid < NE) g_cnt[tid] = 0;
    for (int i = tid; i < TT * 2 * 2; i += gridDim.x * blockDim.x) g_sums[i] = 0.f;
}

// ---------------- 0b: weight fp32 -> fp16 ------------------------------------
__global__ __launch_bounds__(256) void wconv_kernel(const float* __restrict__ w1,
                                                    const float* __restrict__ w2) {
    const float* src = blockIdx.y ? w2 : w1;
    __half* dst = blockIdx.y ? g_w2h : g_w1h;   // device-side symbol resolution
    const int n4 = NE * DN * HN / 4;
    for (int i = blockIdx.x * blockDim.x + threadIdx.x; i < n4;
         i += gridDim.x * blockDim.x) {
        float4 v = ((const float4*)src)[i];
        ((uint2*)dst)[i] = make_uint2(f2h2(v.x, v.y), f2h2(v.z, v.w));
    }
}

// ---------------- 1: gating --------------------------------------------------
__global__ __launch_bounds__(256) void gate_kernel(const float* __restrict__ x,
                                                   const float* __restrict__ gw) {
    int t = blockIdx.x * 8 + (threadIdx.x >> 5);
    if (t >= TT) return;
    int lane = threadIdx.x & 31;
    float acc[NE];
#pragma unroll
    for (int e = 0; e < NE; e++) acc[e] = 0.f;
    const float* xr = x + (size_t)t * DN;
    for (int i = lane; i < DN; i += 32) {
        float xv = xr[i];
        const float4 ga = *(const float4*)(gw + (size_t)i * NE);
        const float4 gb = *(const float4*)(gw + (size_t)i * NE + 4);
        acc[0] = fmaf(xv, ga.x, acc[0]); acc[1] = fmaf(xv, ga.y, acc[1]);
        acc[2] = fmaf(xv, ga.z, acc[2]); acc[3] = fmaf(xv, ga.w, acc[3]);
        acc[4] = fmaf(xv, gb.x, acc[4]); acc[5] = fmaf(xv, gb.y, acc[5]);
        acc[6] = fmaf(xv, gb.z, acc[6]); acc[7] = fmaf(xv, gb.w, acc[7]);
    }
#pragma unroll
    for (int e = 0; e < NE; e++)
        for (int off = 16; off; off >>= 1)
            acc[e] += __shfl_xor_sync(0xffffffffu, acc[e], off);
    if (lane == 0) {
        int i0 = 0; float v0 = acc[0];
#pragma unroll
        for (int e = 1; e < NE; e++) if (acc[e] > v0) { v0 = acc[e]; i0 = e; }
        int i1 = -1; float v1 = -1e30f;
#pragma unroll
        for (int e = 0; e < NE; e++) if (e != i0 && acc[e] > v1) { v1 = acc[e]; i1 = e; }
        float ee = __expf(v1 - v0);
        float w0 = 1.f / (1.f + ee);
        float w1 = ee / (1.f + ee);
        int id0 = t * 2, id1 = t * 2 + 1;
        g_wk[id0] = w0; g_wk[id1] = w1;
        g_eid[id0] = (unsigned char)i0; g_eid[id1] = (unsigned char)i1;
        int s0 = atomicAdd(&g_cnt[i0], 1); g_list[i0 * TT + s0] = id0;
        int s1 = atomicAdd(&g_cnt[i1], 1); g_list[i1 * TT + s1] = id1;
    }
}

// ---------------- fp16 mma grouped GEMM (R5 pipeline structure) --------------
// FIRST: A = x fp32 (row id>>1), W = g_w1h, Out = g_h fp16 (+stats).
// !FIRST: A = g_h fp16 (row id),  W = g_w2h, Out = g_y fp32.
template <int KDIM, int LDN, bool FIRST>
__global__ __launch_bounds__(256) void moe_gemm_h(const float* __restrict__ Araw,
                                                  const float* __restrict__ Bias) {
    const int e = blockIdx.y;
    const int cnt = g_cnt[e];
    const int rowbase = blockIdx.x * TMM;
    if (rowbase >= cnt) return;
    const int n0 = blockIdx.z * TNN;

    // resolve weight symbol IN DEVICE CODE (host-passed __device__ symbols are
    // host-shadow addresses -> ATS reads host zeros; that was the R6/R7 bug)
    const __half* __restrict__ Wh = FIRST ? g_w1h : g_w2h;

    __shared__ __align__(16) __half As[TMM][ASTRIDE];
    __shared__ __align__(16) __half Bs[BKK][BSTRIDE];
    __shared__ int rows_s[TMM];

    const int tid = threadIdx.x;
    if (tid < TMM) {
        int r = rowbase + tid;
        rows_s[tid] = (r < cnt) ? g_list[e * TT + r] : -1;
    }
    __syncthreads();

    // ---- staging maps: A: 4 rows (rb+32i), 4 elems at q*4 ------------------
    const int q = tid & 7, rb = tid >> 3;
    const float* aptrF[4];
    const __half* aptrH[4];
#pragma unroll
    for (int i = 0; i < 4; i++) {
        int id = rows_s[rb + 32 * i];
        if (FIRST) {
            int r = (id < 0) ? 0 : (id >> 1);
            aptrF[i] = Araw + (size_t)r * KDIM + q * 4;
        } else {
            int r = (id < 0) ? 0 : id;
            aptrH[i] = g_h + (size_t)r * KDIM + q * 4;
        }
    }
    // B: row k = tid>>3, 16 halfs at (tid&7)*16
    const int bkr = tid >> 3;
    const int bnc = (tid & 7) * 16;
    const __half* bptr = Wh + (size_t)e * KDIM * LDN + (size_t)bkr * LDN + n0 + bnc;

    const int lane = tid & 31;
    const int wid = tid >> 5;
    const int wm = (wid >> 1) * 32;
    const int wn = (wid & 1) * 64;
    const int g = lane >> 2, t4 = lane & 3;

    const uint32_t as_b = smem_u32(&As[0][0]);
    const uint32_t bs_b = smem_u32(&Bs[0][0]);
    const uint32_t a_addr0 = as_b + ((wm + (lane & 15)) * ASTRIDE + ((lane >> 4) << 3)) * 2;
    const uint32_t b_addr0 = bs_b + (((lane & 7) + ((lane & 8) ? 8 : 0)) * BSTRIDE +
                                     wn + ((lane & 16) ? 8 : 0)) * 2;

    float c[2][8][4];
#pragma unroll
    for (int mt = 0; mt < 2; mt++)
#pragma unroll
        for (int nt = 0; nt < 8; nt++)
#pragma unroll
            for (int r = 0; r < 4; r++) c[mt][nt][r] = 0.f;

    float4 paF[4];
    uint2 paH[4];
    uint4 pb0, pb1;
    if (FIRST) {
#pragma unroll
        for (int i = 0; i < 4; i++) paF[i] = *(const float4*)(aptrF[i]);
    } else {
#pragma unroll
        for (int i = 0; i < 4; i++) paH[i] = *(const uint2*)(aptrH[i]);
    }
    pb0 = *(const uint4*)(bptr);
    pb1 = *(const uint4*)(bptr + 8);

    const int NK = KDIM / BKK;
    for (int ch = 0; ch < NK; ++ch) {
        __syncthreads();   // previous mma done reading smem
        // ---- STS chunk ch ----
        if (FIRST) {
#pragma unroll
            for (int i = 0; i < 4; i++)
                *(uint2*)&As[rb + 32 * i][q * 4] =
                    make_uint2(f2h2(paF[i].x, paF[i].y), f2h2(paF[i].z, paF[i].w));
        } else {
#pragma unroll
            for (int i = 0; i < 4; i++)
                *(uint2*)&As[rb + 32 * i][q * 4] = paH[i];
        }
        *(uint4*)&Bs[bkr][bnc] = pb0;
        *(uint4*)&Bs[bkr][bnc + 8] = pb1;
        __syncthreads();
        // ---- prefetch next chunk ----
        if (ch + 1 < NK) {
            const int k0 = (ch + 1) * BKK;
            if (FIRST) {
#pragma unroll
                for (int i = 0; i < 4; i++) paF[i] = *(const float4*)(aptrF[i] + k0);
            } else {
#pragma unroll
                for (int i = 0; i < 4; i++) paH[i] = *(const uint2*)(aptrH[i] + k0);
            }
            const __half* bp = bptr + (size_t)k0 * LDN;
            pb0 = *(const uint4*)(bp);
            pb1 = *(const uint4*)(bp + 8);
        }
        // ---- 2 x k16 mma steps ----
#pragma unroll
        for (int ks = 0; ks < 2; ks++) {
            const int kc = ks * 16;
            uint32_t af[2][4];
#pragma unroll
            for (int mt = 0; mt < 2; mt++)
                ldsm4(af[mt][0], af[mt][1], af[mt][2], af[mt][3],
                      a_addr0 + (mt * 16 * ASTRIDE + kc) * 2);
            uint32_t bf[8][2];
#pragma unroll
            for (int np = 0; np < 4; np++) {
                uint32_t r0, r1, r2, r3;
                ldsm4t(r0, r1, r2, r3, b_addr0 + (kc * BSTRIDE + np * 16) * 2);
                bf[2 * np][0] = r0; bf[2 * np][1] = r1;
                bf[2 * np + 1][0] = r2; bf[2 * np + 1][1] = r3;
            }
#pragma unroll
            for (int mt = 0; mt < 2; mt++)
#pragma unroll
                for (int nt = 0; nt < 8; nt++)
                    mma16(c[mt][nt], af[mt], bf[nt][0], bf[nt][1]);
        }
    }

    // ---- epilogue ----
    const float* be = Bias + (size_t)e * LDN + n0;
#pragma unroll
    for (int mt = 0; mt < 2; mt++) {
        int r0l = wm + mt * 16 + g;
        int r1l = r0l + 8;
        int id0 = rows_s[r0l], id1 = rows_s[r1l];
        float s0 = 0.f, q0 = 0.f, s1 = 0.f, q1 = 0.f;
#pragma unroll
        for (int nt = 0; nt < 8; nt++) {
            int col = wn + nt * 8 + 2 * t4;
            float bx = be[col], by = be[col + 1];
            float v00 = c[mt][nt][0] + bx, v01 = c[mt][nt][1] + by;
            float v10 = c[mt][nt][2] + bx, v11 = c[mt][nt][3] + by;
            if (FIRST) {
                s0 += v00 + v01; q0 += v00 * v00 + v01 * v01;
                s1 += v10 + v11; q1 += v10 * v10 + v11 * v11;
                if (id0 >= 0)
                    *(__half2*)(g_h + (size_t)id0 * LDN + n0 + col) =
                        __floats2half2_rn(v00, v01);
                if (id1 >= 0)
                    *(__half2*)(g_h + (size_t)id1 * LDN + n0 + col) =
                        __floats2half2_rn(v10, v11);
            } else {
                if (id0 >= 0)
                    *(float2*)(g_y + (size_t)id0 * LDN + n0 + col) = make_float2(v00, v01);
                if (id1 >= 0)
                    *(float2*)(g_y + (size_t)id1 * LDN + n0 + col) = make_float2(v10, v11);
            }
        }
        if (FIRST) {
#pragma unroll
            for (int off = 1; off <= 2; off <<= 1) {
                s0 += __shfl_xor_sync(0xffffffffu, s0, off);
                q0 += __shfl_xor_sync(0xffffffffu, q0, off);
                s1 += __shfl_xor_sync(0xffffffffu, s1, off);
                q1 += __shfl_xor_sync(0xffffffffu, q1, off);
            }
            if (t4 == 0) {
                if (id0 >= 0) { atomicAdd(&g_sums[2 * id0], s0); atomicAdd(&g_sums[2 * id0 + 1], q0); }
                if (id1 >= 0) { atomicAdd(&g_sums[2 * id1], s1); atomicAdd(&g_sums[2 * id1 + 1], q1); }
            }
        }
    }
}

// ---------------- 3: LN1 + exact GeLU (fp16 in/out) --------------------------
__global__ __launch_bounds__(256) void act_kernel(const float* __restrict__ ln1_g,
                                                  const float* __restrict__ ln1_b) {
    const int id = blockIdx.x;
    const int e = g_eid[id];
    float sum = g_sums[2 * id], sq = g_sums[2 * id + 1];
    float mean = sum * (1.f / HN);
    float var = sq * (1.f / HN) - mean * mean;
    float rstd = rsqrtf(var + EPSV);
    __half2* hr = (__half2*)(g_h + (size_t)id * HN);
    const float2* gg = (const float2*)(ln1_g + (size_t)e * HN);
    const float2* bb = (const float2*)(ln1_b + (size_t)e * HN);
    for (int i = threadIdx.x; i < HN / 2; i += blockDim.x) {
        float2 h2 = __half22float2(hr[i]);
        float2 g2 = gg[i], b2 = bb[i];
        float v0 = (h2.x - mean) * rstd * g2.x + b2.x;
        float v1 = (h2.y - mean) * rstd * g2.y + b2.y;
        v0 = v0 * normcdff(v0);
        v1 = v1 * normcdff(v1);
        hr[i] = __floats2half2_rn(v0, v1);
    }
}

// ---------------- 5: combine + residual + final LN ---------------------------
__global__ __launch_bounds__(256) void final_kernel(const float* __restrict__ x,
                                                    const float* __restrict__ ln_g,
                                                    const float* __restrict__ ln_b,
                                                    float* __restrict__ out) {
    const int t = blockIdx.x;
    __shared__ __align__(16) float s[DN];
    __shared__ float red[2][8];
    const float w0 = g_wk[2 * t], w1v = g_wk[2 * t + 1];
    const float* y0 = g_y + (size_t)(2 * t) * DN;
    const float* y1 = g_y + (size_t)(2 * t + 1) * DN;
    const float* xr = x + (size_t)t * DN;
    float ls = 0.f, lq = 0.f;
    for (int i = threadIdx.x; i < DN; i += blockDim.x) {
        float v = xr[i] + w0 * y0[i] + w1v * y1[i];
        s[i] = v; ls += v; lq += v * v;
    }
    int lane = threadIdx.x & 31, wid = threadIdx.x >> 5;
    for (int off = 16; off; off >>= 1) {
        ls += __shfl_down_sync(0xffffffffu, ls, off);
        lq += __shfl_down_sync(0xffffffffu, lq, off);
    }
    if (lane == 0) { red[0][wid] = ls; red[1][wid] = lq; }
    __syncthreads();
    if (wid == 0) {
        ls = (lane < 8) ? red[0][lane] : 0.f;
        lq = (lane < 8) ? red[1][lane] : 0.f;
        for (int off = 4; off; off >>= 1) {
            ls += __shfl_down_sync(0xffffffffu, ls, off);
            lq += __shfl_down_sync(0xffffffffu, lq, off);
        }
        if (lane == 0) { red[0][0] = ls; red[1][0] = lq; }
    }
    __syncthreads();
    float mean = red[0][0] * (1.f / DN);
    float var = red[1][0] * (1.f / DN) - mean * mean;
    float rstd = rsqrtf(var + EPSV);
    for (int i = threadIdx.x; i < DN; i += blockDim.x)
        out[(size_t)t * DN + i] = (s[i] - mean) * rstd * ln_g[i] + ln_b[i];
}

// ---------------- launch -----------------------------------------------------
extern "C" void kernel_launch(void* const* d_in, const int* in_sizes, int n_in,
                              void* d_out, int out_size) {
    const float* x      = (const float*)d_in[0];
    const float* gate_w = (const float*)d_in[1];
    const float* w1     = (const float*)d_in[2];
    const float* b1     = (const float*)d_in[3];
    const float* ln1_g  = (const float*)d_in[4];
    const float* ln1_b  = (const float*)d_in[5];
    const float* w2     = (const float*)d_in[6];
    const float* b2     = (const float*)d_in[7];
    const float* ln_g   = (const float*)d_in[8];
    const float* ln_b   = (const float*)d_in[9];
    float* out = (float*)d_out;

    zero_kernel<<<64, 256>>>();
    wconv_kernel<<<dim3(2048, 2), 256>>>(w1, w2);
    gate_kernel<<<TT / 8, 256>>>(x, gate_w);
    moe_gemm_h<DN, HN, true><<<dim3(TT / TMM, NE, HN / TNN), 256>>>(x, b1);
    act_kernel<<<TT * 2, 256>>>(ln1_g, ln1_b);
    moe_gemm_h<HN, DN, false><<<dim3(TT / TMM, NE, DN / TNN), 256>>>(nullptr, b2);
    final_kernel<<<TT, 256>>>(x, ln_g, ln_b, out);
}